// round 1
// baseline (speedup 1.0000x reference)
#include <cuda_runtime.h>
#include <math.h>

// ---------------- problem constants ----------------
#define BB   2
#define LL   1024
#define DD   768
#define VV   32000
#define NLAYER 4
#define DIN  1536          // d_inner
#define NS   16            // d_state
#define DCV  4             // d_conv
#define DTR  48            // dt_rank
#define XDIM (DTR + 2*NS)  // 80
#define MROWS (BB*LL)      // 2048

// ---------------- device scratch (no allocation allowed) ----------------
__device__ float g_x   [MROWS*DD];      // residual stream
__device__ float g_xn  [MROWS*DD];      // rmsnorm output
__device__ float g_xz  [MROWS*2*DIN];   // in_proj output (xb | z)
__device__ float g_xbc [MROWS*DIN];     // conv+silu output (u)
__device__ float g_xdbl[MROWS*XDIM];    // x_proj output (dt | B | C)
__device__ float g_dlt [MROWS*DIN];     // softplus(dt@dtw + b)
__device__ float g_y   [MROWS*DIN];     // scan output * silu(z)

// ---------------- helpers ----------------
__device__ __forceinline__ float softplusf(float x) {
    return fmaxf(x, 0.f) + log1pf(expf(-fabsf(x)));
}
__device__ __forceinline__ float siluf(float x) {
    return x / (1.f + expf(-x));
}

// ---------------- embedding gather ----------------
__global__ void embed_kernel(const int* __restrict__ tok,
                             const float* __restrict__ emb) {
    int idx = blockIdx.x * blockDim.x + threadIdx.x;
    if (idx >= MROWS * DD) return;
    int row = idx / DD, d = idx - row * DD;
    g_x[idx] = emb[tok[row] * DD + d];
}

// ---------------- rmsnorm: one block per row ----------------
__global__ void rmsnorm_kernel(const float* __restrict__ w) {
    int row = blockIdx.x;
    const float* xr = g_x + row * DD;
    float s = 0.f;
    for (int i = threadIdx.x; i < DD; i += 256) { float v = xr[i]; s += v * v; }
    __shared__ float red[8];
    #pragma unroll
    for (int o = 16; o; o >>= 1) s += __shfl_xor_sync(~0u, s, o);
    if ((threadIdx.x & 31) == 0) red[threadIdx.x >> 5] = s;
    __syncthreads();
    if (threadIdx.x < 8) {
        float v = red[threadIdx.x];
        #pragma unroll
        for (int o = 4; o; o >>= 1) v += __shfl_xor_sync(0xff, v, o);
        if (threadIdx.x == 0) red[0] = v;
    }
    __syncthreads();
    float rstd = rsqrtf(red[0] / (float)DD + 1e-5f);
    for (int i = threadIdx.x; i < DD; i += 256)
        g_xn[row * DD + i] = xr[i] * rstd * w[i];
}

// ---------------- causal depthwise conv (DC=4) + silu ----------------
__global__ void conv_silu_kernel(const float* __restrict__ w,
                                 const float* __restrict__ bias) {
    int idx = blockIdx.x * blockDim.x + threadIdx.x;
    if (idx >= MROWS * DIN) return;
    int c = idx % DIN;
    int row = idx / DIN;          // row = b*LL + t
    int t = row % LL;
    float acc = bias[c];
    #pragma unroll
    for (int j = 0; j < DCV; j++) {
        int tt = t - (DCV - 1) + j;
        if (tt >= 0)
            acc += w[c * DCV + j] * g_xz[(row - (DCV - 1) + j) * (2 * DIN) + c];
    }
    g_xbc[idx] = siluf(acc);
}

// ---------------- generic SGEMM: C[M,N] = A[M,K] @ W[N,K]^T (+bias)(+act)(+resid)
// 128x128 tile, BK=8, 8x8 per thread, 256 threads.
// Assumes M % 128 == 0, K % 8 == 0, 16B-aligned rows (lda*4 % 16 == 0). N guarded.
__global__ void __launch_bounds__(256)
sgemm_kernel(const float* __restrict__ A, const float* __restrict__ W,
             const float* __restrict__ bias, const float* __restrict__ resid,
             float* __restrict__ C,
             int M, int N, int K, int lda, int ldc, int act) {
    __shared__ __align__(16) float As[8][128];
    __shared__ __align__(16) float Bs[8][128];
    int tid = threadIdx.x;
    int m0 = blockIdx.y * 128, n0 = blockIdx.x * 128;
    int tr = tid / 16, tc = tid % 16;

    int lrow = tid >> 1;
    int lcol = (tid & 1) * 4;
    const float* Aptr = A + (size_t)(m0 + lrow) * lda + lcol;
    bool wvalid = (n0 + lrow) < N;
    const float* Wptr = W + (size_t)(n0 + lrow) * K + lcol;

    float acc[8][8];
    #pragma unroll
    for (int i = 0; i < 8; i++)
        #pragma unroll
        for (int j = 0; j < 8; j++) acc[i][j] = 0.f;

    for (int k0 = 0; k0 < K; k0 += 8) {
        float4 av = *(const float4*)(Aptr + k0);
        float4 wv = wvalid ? *(const float4*)(Wptr + k0)
                           : make_float4(0.f, 0.f, 0.f, 0.f);
        As[lcol + 0][lrow] = av.x; As[lcol + 1][lrow] = av.y;
        As[lcol + 2][lrow] = av.z; As[lcol + 3][lrow] = av.w;
        Bs[lcol + 0][lrow] = wv.x; Bs[lcol + 1][lrow] = wv.y;
        Bs[lcol + 2][lrow] = wv.z; Bs[lcol + 3][lrow] = wv.w;
        __syncthreads();
        #pragma unroll
        for (int kk = 0; kk < 8; kk++) {
            float4 ra0 = *(const float4*)&As[kk][tr * 8];
            float4 ra1 = *(const float4*)&As[kk][tr * 8 + 4];
            float4 rb0 = *(const float4*)&Bs[kk][tc * 8];
            float4 rb1 = *(const float4*)&Bs[kk][tc * 8 + 4];
            float ra[8] = {ra0.x, ra0.y, ra0.z, ra0.w, ra1.x, ra1.y, ra1.z, ra1.w};
            float rb[8] = {rb0.x, rb0.y, rb0.z, rb0.w, rb1.x, rb1.y, rb1.z, rb1.w};
            #pragma unroll
            for (int i = 0; i < 8; i++)
                #pragma unroll
                for (int j = 0; j < 8; j++)
                    acc[i][j] += ra[i] * rb[j];
        }
        __syncthreads();
    }

    #pragma unroll
    for (int i = 0; i < 8; i++) {
        int m = m0 + tr * 8 + i;
        #pragma unroll
        for (int j = 0; j < 8; j++) {
            int n = n0 + tc * 8 + j;
            if (n < N) {
                float v = acc[i][j];
                if (bias)  v += bias[n];
                if (act == 1) v = softplusf(v);
                if (resid) v += resid[(size_t)m * ldc + n];
                C[(size_t)m * ldc + n] = v;
            }
        }
    }
}

// ---------------- selective scan: half-warp (16 lanes = 16 states) per (b,d)
// y = (scan(u, delta, A, B, C) + u*Dv) * silu(z)
__global__ void scan_kernel(const float* __restrict__ A_log,
                            const float* __restrict__ Dvec) {
    int half = threadIdx.x / 16;               // 0..15 within block
    int ch = blockIdx.x * 16 + half;           // 0..B*DIN-1
    int lane = threadIdx.x & 15;
    int b = ch / DIN, d = ch % DIN;

    float An = -__expf(A_log[d * NS + lane]);
    float Dd = Dvec[d];

    const float* dptr = g_dlt  + (size_t)b * LL * DIN + d;
    const float* uptr = g_xbc  + (size_t)b * LL * DIN + d;
    const float* bptr = g_xdbl + (size_t)b * LL * XDIM + DTR + lane;
    const float* cptr = g_xdbl + (size_t)b * LL * XDIM + DTR + NS + lane;
    const float* zptr = g_xz   + (size_t)b * LL * (2 * DIN) + DIN + d;
    float* yptr = g_y + (size_t)b * LL * DIN + d;

    float h = 0.f;
    for (int t = 0; t < LL; t++) {
        float delta = dptr[(size_t)t * DIN];
        float u     = uptr[(size_t)t * DIN];
        float Bn    = bptr[(size_t)t * XDIM];
        float Cn    = cptr[(size_t)t * XDIM];
        float dA = __expf(delta * An);
        h = dA * h + delta * Bn * u;
        float p = h * Cn;
        p += __shfl_xor_sync(~0u, p, 8);
        p += __shfl_xor_sync(~0u, p, 4);
        p += __shfl_xor_sync(~0u, p, 2);
        p += __shfl_xor_sync(~0u, p, 1);
        if (lane == 0) {
            float z = zptr[(size_t)t * (2 * DIN)];
            float yv = p + u * Dd;
            yv *= z / (1.f + __expf(-z));
            yptr[(size_t)t * DIN] = yv;
        }
    }
}

// ---------------- launch ----------------
extern "C" void kernel_launch(void* const* d_in, const int* in_sizes, int n_in,
                              void* d_out, int out_size) {
    const int*   tokens    = (const int*)  d_in[0];
    const float* emb       = (const float*)d_in[1];
    const float* Wout_w    = (const float*)d_in[2];
    const float* Wout_b    = (const float*)d_in[3];
    const float* norm_w    = (const float*)d_in[4];
    const float* in_proj_w = (const float*)d_in[5];
    const float* conv_w    = (const float*)d_in[6];
    const float* conv_b    = (const float*)d_in[7];
    const float* x_proj_w  = (const float*)d_in[8];
    const float* dt_proj_w = (const float*)d_in[9];
    const float* dt_proj_b = (const float*)d_in[10];
    const float* A_log     = (const float*)d_in[11];
    const float* Dvec      = (const float*)d_in[12];
    const float* out_projw = (const float*)d_in[13];
    float* out = (float*)d_out;

    float *x, *xn, *xz, *xbc, *xdbl, *dlt, *y;
    cudaGetSymbolAddress((void**)&x,    g_x);
    cudaGetSymbolAddress((void**)&xn,   g_xn);
    cudaGetSymbolAddress((void**)&xz,   g_xz);
    cudaGetSymbolAddress((void**)&xbc,  g_xbc);
    cudaGetSymbolAddress((void**)&xdbl, g_xdbl);
    cudaGetSymbolAddress((void**)&dlt,  g_dlt);
    cudaGetSymbolAddress((void**)&y,    g_y);

    embed_kernel<<<(MROWS * DD + 255) / 256, 256>>>(tokens, emb);

    for (int l = 0; l < NLAYER; l++) {
        rmsnorm_kernel<<<MROWS, 256>>>(norm_w + (size_t)l * DD);

        // in_proj: (2048 x 3072), K=768
        {
            dim3 g(2 * DIN / 128, MROWS / 128);
            sgemm_kernel<<<g, 256>>>(xn, in_proj_w + (size_t)l * 2 * DIN * DD,
                                     nullptr, nullptr, xz,
                                     MROWS, 2 * DIN, DD, DD, 2 * DIN, 0);
        }

        conv_silu_kernel<<<(MROWS * DIN + 255) / 256, 256>>>(
            conv_w + (size_t)l * DIN * DCV, conv_b + (size_t)l * DIN);

        // x_proj: (2048 x 80), K=1536
        {
            dim3 g((XDIM + 127) / 128, MROWS / 128);
            sgemm_kernel<<<g, 256>>>(xbc, x_proj_w + (size_t)l * XDIM * DIN,
                                     nullptr, nullptr, xdbl,
                                     MROWS, XDIM, DIN, DIN, XDIM, 0);
        }

        // dt_proj + bias + softplus: (2048 x 1536), K=48, A = x_dbl[:, 0:48]
        {
            dim3 g(DIN / 128, MROWS / 128);
            sgemm_kernel<<<g, 256>>>(xdbl, dt_proj_w + (size_t)l * DIN * DTR,
                                     dt_proj_b + (size_t)l * DIN, nullptr, dlt,
                                     MROWS, DIN, DTR, XDIM, DIN, 1);
        }

        scan_kernel<<<(BB * DIN) / 16, 256>>>(A_log + (size_t)l * DIN * NS,
                                              Dvec + (size_t)l * DIN);

        // out_proj + residual: (2048 x 768), K=1536, C = resid = x
        {
            dim3 g(DD / 128, MROWS / 128);
            sgemm_kernel<<<g, 256>>>(y, out_projw + (size_t)l * DD * DIN,
                                     nullptr, x, x,
                                     MROWS, DD, DIN, DIN, DD, 0);
        }
    }

    // logits: (2048 x 32000), K=768, + bias
    {
        dim3 g(VV / 128, MROWS / 128);
        sgemm_kernel<<<g, 256>>>(x, Wout_w, Wout_b, nullptr, out,
                                 MROWS, VV, DD, DD, VV, 0);
    }
}

// round 2
// speedup vs baseline: 1.6997x; 1.6997x over previous
#include <cuda_runtime.h>
#include <math.h>
#include <stdint.h>

// ---------------- problem constants ----------------
#define BB   2
#define LL   1024
#define DD   768
#define VV   32000
#define NLAYER 4
#define DIN  1536          // d_inner
#define NS   16            // d_state
#define DCV  4             // d_conv
#define DTR  48            // dt_rank
#define XDIM (DTR + 2*NS)  // 80
#define MROWS (BB*LL)      // 2048

// ---------------- device scratch (no allocation allowed) ----------------
__device__ float g_x   [MROWS*DD];      // residual stream
__device__ float g_xn  [MROWS*DD];      // rmsnorm output
__device__ float g_xz  [MROWS*2*DIN];   // in_proj output (xb | z)
__device__ float g_xbc [MROWS*DIN];     // conv+silu output (u)
__device__ float g_xdbl[MROWS*XDIM];    // x_proj output (dt | B | C)
__device__ float g_dlt [MROWS*DIN];     // softplus(dt@dtw + b)
__device__ float g_y   [MROWS*DIN];     // scan output * silu(z)

// ---------------- helpers ----------------
__device__ __forceinline__ float softplusf(float x) {
    return fmaxf(x, 0.f) + log1pf(expf(-fabsf(x)));
}
__device__ __forceinline__ float siluf(float x) {
    return x / (1.f + expf(-x));
}
__device__ __forceinline__ uint32_t to_tf32(float f) {
    uint32_t u;
    asm("cvt.rna.tf32.f32 %0, %1;" : "=r"(u) : "f"(f));
    return u;
}

// ---------------- embedding gather ----------------
__global__ void embed_kernel(const int* __restrict__ tok,
                             const float* __restrict__ emb) {
    int idx = blockIdx.x * blockDim.x + threadIdx.x;
    if (idx >= MROWS * DD) return;
    int row = idx / DD, d = idx - row * DD;
    g_x[idx] = emb[tok[row] * DD + d];
}

// ---------------- rmsnorm: one block per row ----------------
__global__ void rmsnorm_kernel(const float* __restrict__ w) {
    int row = blockIdx.x;
    const float* xr = g_x + row * DD;
    float s = 0.f;
    for (int i = threadIdx.x; i < DD; i += 256) { float v = xr[i]; s += v * v; }
    __shared__ float red[8];
    #pragma unroll
    for (int o = 16; o; o >>= 1) s += __shfl_xor_sync(~0u, s, o);
    if ((threadIdx.x & 31) == 0) red[threadIdx.x >> 5] = s;
    __syncthreads();
    if (threadIdx.x < 8) {
        float v = red[threadIdx.x];
        #pragma unroll
        for (int o = 4; o; o >>= 1) v += __shfl_xor_sync(0xff, v, o);
        if (threadIdx.x == 0) red[0] = v;
    }
    __syncthreads();
    float rstd = rsqrtf(red[0] / (float)DD + 1e-5f);
    for (int i = threadIdx.x; i < DD; i += 256)
        g_xn[row * DD + i] = xr[i] * rstd * w[i];
}

// ---------------- causal depthwise conv (DC=4) + silu ----------------
__global__ void conv_silu_kernel(const float* __restrict__ w,
                                 const float* __restrict__ bias) {
    int idx = blockIdx.x * blockDim.x + threadIdx.x;
    if (idx >= MROWS * DIN) return;
    int c = idx % DIN;
    int row = idx / DIN;          // row = b*LL + t
    int t = row % LL;
    float acc = bias[c];
    #pragma unroll
    for (int j = 0; j < DCV; j++) {
        int tt = t - (DCV - 1) + j;
        if (tt >= 0)
            acc += w[c * DCV + j] * g_xz[(row - (DCV - 1) + j) * (2 * DIN) + c];
    }
    g_xbc[idx] = siluf(acc);
}

// ---------------- TF32 tensor-core GEMM ----------------
// C[M,N] = A[M,K] @ W[N,K]^T (+bias)(+softplus)(+resid)
// Tile 128x128, BK=16, 8 warps (each warp 64x32 via 4x4 m16n8k8 mma).
// Requires: M%128==0, K%16==0, lda%4==0 (rows 16B aligned). N guarded.
__global__ void __launch_bounds__(256)
tgemm_kernel(const float* __restrict__ A, const float* __restrict__ W,
             const float* __restrict__ bias, const float* __restrict__ resid,
             float* __restrict__ C,
             int M, int N, int K, int lda, int ldc, int act) {
    __shared__ uint32_t As[128][20];   // [m][k] pad->conflict-free
    __shared__ uint32_t Bs[128][20];   // [n][k]

    int tid = threadIdx.x;
    int m0 = blockIdx.y * 128, n0 = blockIdx.x * 128;
    int lane = tid & 31, warp = tid >> 5;
    int wm = (warp & 1) * 64;          // warp m-offset
    int wn = (warp >> 1) * 32;         // warp n-offset

    int sr = tid >> 2;                 // 0..63 staging row
    int sc = (tid & 3) * 4;            // staging k-col (0,4,8,12)

    const float* Aptr0 = A + (size_t)(m0 + sr) * lda + sc;
    const float* Aptr1 = A + (size_t)(m0 + sr + 64) * lda + sc;
    bool wv0 = (n0 + sr) < N;
    bool wv1 = (n0 + sr + 64) < N;
    const float* Wptr0 = W + (size_t)(n0 + sr) * K + sc;
    const float* Wptr1 = W + (size_t)(n0 + sr + 64) * K + sc;

    float acc[4][4][4];
    #pragma unroll
    for (int i = 0; i < 4; i++)
        #pragma unroll
        for (int j = 0; j < 4; j++)
            #pragma unroll
            for (int r = 0; r < 4; r++) acc[i][j][r] = 0.f;

    for (int ks = 0; ks < K; ks += 16) {
        // stage A
        {
            float4 a0 = *(const float4*)(Aptr0 + ks);
            float4 a1 = *(const float4*)(Aptr1 + ks);
            As[sr][sc + 0] = to_tf32(a0.x); As[sr][sc + 1] = to_tf32(a0.y);
            As[sr][sc + 2] = to_tf32(a0.z); As[sr][sc + 3] = to_tf32(a0.w);
            As[sr + 64][sc + 0] = to_tf32(a1.x); As[sr + 64][sc + 1] = to_tf32(a1.y);
            As[sr + 64][sc + 2] = to_tf32(a1.z); As[sr + 64][sc + 3] = to_tf32(a1.w);
        }
        // stage W (zero-fill invalid rows)
        {
            float4 w0 = wv0 ? *(const float4*)(Wptr0 + ks) : make_float4(0,0,0,0);
            float4 w1 = wv1 ? *(const float4*)(Wptr1 + ks) : make_float4(0,0,0,0);
            Bs[sr][sc + 0] = to_tf32(w0.x); Bs[sr][sc + 1] = to_tf32(w0.y);
            Bs[sr][sc + 2] = to_tf32(w0.z); Bs[sr][sc + 3] = to_tf32(w0.w);
            Bs[sr + 64][sc + 0] = to_tf32(w1.x); Bs[sr + 64][sc + 1] = to_tf32(w1.y);
            Bs[sr + 64][sc + 2] = to_tf32(w1.z); Bs[sr + 64][sc + 3] = to_tf32(w1.w);
        }
        __syncthreads();

        #pragma unroll
        for (int kk = 0; kk < 16; kk += 8) {
            uint32_t af[4][4], bf[4][2];
            int k0 = kk + (lane & 3);
            int fr = lane >> 2;            // 0..7
            #pragma unroll
            for (int mt = 0; mt < 4; mt++) {
                int row = wm + mt * 16 + fr;
                af[mt][0] = As[row][k0];
                af[mt][1] = As[row + 8][k0];
                af[mt][2] = As[row][k0 + 4];
                af[mt][3] = As[row + 8][k0 + 4];
            }
            #pragma unroll
            for (int nt = 0; nt < 4; nt++) {
                int col = wn + nt * 8 + fr;
                bf[nt][0] = Bs[col][k0];
                bf[nt][1] = Bs[col][k0 + 4];
            }
            #pragma unroll
            for (int mt = 0; mt < 4; mt++)
                #pragma unroll
                for (int nt = 0; nt < 4; nt++) {
                    asm volatile(
                        "mma.sync.aligned.m16n8k8.row.col.f32.tf32.tf32.f32 "
                        "{%0,%1,%2,%3}, {%4,%5,%6,%7}, {%8,%9}, {%0,%1,%2,%3};"
                        : "+f"(acc[mt][nt][0]), "+f"(acc[mt][nt][1]),
                          "+f"(acc[mt][nt][2]), "+f"(acc[mt][nt][3])
                        : "r"(af[mt][0]), "r"(af[mt][1]),
                          "r"(af[mt][2]), "r"(af[mt][3]),
                          "r"(bf[nt][0]), "r"(bf[nt][1]));
                }
        }
        __syncthreads();
    }

    // epilogue
    int fr = lane >> 2;
    int fc = (lane & 3) * 2;
    #pragma unroll
    for (int mt = 0; mt < 4; mt++) {
        int row0 = m0 + wm + mt * 16 + fr;
        #pragma unroll
        for (int nt = 0; nt < 4; nt++) {
            int col0 = n0 + wn + nt * 8 + fc;
            #pragma unroll
            for (int r = 0; r < 4; r++) {
                int m = row0 + (r >> 1) * 8;
                int n = col0 + (r & 1);
                if (n < N) {
                    float v = acc[mt][nt][r];
                    if (bias) v += bias[n];
                    if (act == 1) v = softplusf(v);
                    if (resid) v += resid[(size_t)m * ldc + n];
                    C[(size_t)m * ldc + n] = v;
                }
            }
        }
    }
}

// ---------------- selective scan: half-warp (16 lanes = 16 states) per (b,d)
__global__ void scan_kernel(const float* __restrict__ A_log,
                            const float* __restrict__ Dvec) {
    int half = threadIdx.x / 16;
    int ch = blockIdx.x * 16 + half;
    int lane = threadIdx.x & 15;
    int b = ch / DIN, d = ch % DIN;

    float An = -__expf(A_log[d * NS + lane]);
    float Dd = Dvec[d];

    const float* dptr = g_dlt  + (size_t)b * LL * DIN + d;
    const float* uptr = g_xbc  + (size_t)b * LL * DIN + d;
    const float* bptr = g_xdbl + (size_t)b * LL * XDIM + DTR + lane;
    const float* cptr = g_xdbl + (size_t)b * LL * XDIM + DTR + NS + lane;
    const float* zptr = g_xz   + (size_t)b * LL * (2 * DIN) + DIN + d;
    float* yptr = g_y + (size_t)b * LL * DIN + d;

    float h = 0.f;
    for (int t = 0; t < LL; t++) {
        float delta = dptr[(size_t)t * DIN];
        float u     = uptr[(size_t)t * DIN];
        float Bn    = bptr[(size_t)t * XDIM];
        float Cn    = cptr[(size_t)t * XDIM];
        float dA = __expf(delta * An);
        h = dA * h + delta * Bn * u;
        float p = h * Cn;
        p += __shfl_xor_sync(~0u, p, 8);
        p += __shfl_xor_sync(~0u, p, 4);
        p += __shfl_xor_sync(~0u, p, 2);
        p += __shfl_xor_sync(~0u, p, 1);
        if (lane == 0) {
            float z = zptr[(size_t)t * (2 * DIN)];
            float yv = p + u * Dd;
            yv *= z / (1.f + __expf(-z));
            yptr[(size_t)t * DIN] = yv;
        }
    }
}

// ---------------- launch ----------------
extern "C" void kernel_launch(void* const* d_in, const int* in_sizes, int n_in,
                              void* d_out, int out_size) {
    const int*   tokens    = (const int*)  d_in[0];
    const float* emb       = (const float*)d_in[1];
    const float* Wout_w    = (const float*)d_in[2];
    const float* Wout_b    = (const float*)d_in[3];
    const float* norm_w    = (const float*)d_in[4];
    const float* in_proj_w = (const float*)d_in[5];
    const float* conv_w    = (const float*)d_in[6];
    const float* conv_b    = (const float*)d_in[7];
    const float* x_proj_w  = (const float*)d_in[8];
    const float* dt_proj_w = (const float*)d_in[9];
    const float* dt_proj_b = (const float*)d_in[10];
    const float* A_log     = (const float*)d_in[11];
    const float* Dvec      = (const float*)d_in[12];
    const float* out_projw = (const float*)d_in[13];
    float* out = (float*)d_out;

    float *x, *xn, *xz, *xbc, *xdbl, *dlt, *y;
    cudaGetSymbolAddress((void**)&x,    g_x);
    cudaGetSymbolAddress((void**)&xn,   g_xn);
    cudaGetSymbolAddress((void**)&xz,   g_xz);
    cudaGetSymbolAddress((void**)&xbc,  g_xbc);
    cudaGetSymbolAddress((void**)&xdbl, g_xdbl);
    cudaGetSymbolAddress((void**)&dlt,  g_dlt);
    cudaGetSymbolAddress((void**)&y,    g_y);

    embed_kernel<<<(MROWS * DD + 255) / 256, 256>>>(tokens, emb);

    for (int l = 0; l < NLAYER; l++) {
        rmsnorm_kernel<<<MROWS, 256>>>(norm_w + (size_t)l * DD);

        // in_proj: (2048 x 3072), K=768
        {
            dim3 g(2 * DIN / 128, MROWS / 128);
            tgemm_kernel<<<g, 256>>>(xn, in_proj_w + (size_t)l * 2 * DIN * DD,
                                     nullptr, nullptr, xz,
                                     MROWS, 2 * DIN, DD, DD, 2 * DIN, 0);
        }

        conv_silu_kernel<<<(MROWS * DIN + 255) / 256, 256>>>(
            conv_w + (size_t)l * DIN * DCV, conv_b + (size_t)l * DIN);

        // x_proj: (2048 x 80), K=1536
        {
            dim3 g((XDIM + 127) / 128, MROWS / 128);
            tgemm_kernel<<<g, 256>>>(xbc, x_proj_w + (size_t)l * XDIM * DIN,
                                     nullptr, nullptr, xdbl,
                                     MROWS, XDIM, DIN, DIN, XDIM, 0);
        }

        // dt_proj + bias + softplus: (2048 x 1536), K=48, A = x_dbl[:, 0:48]
        {
            dim3 g(DIN / 128, MROWS / 128);
            tgemm_kernel<<<g, 256>>>(xdbl, dt_proj_w + (size_t)l * DIN * DTR,
                                     dt_proj_b + (size_t)l * DIN, nullptr, dlt,
                                     MROWS, DIN, DTR, XDIM, DIN, 1);
        }

        scan_kernel<<<(BB * DIN) / 16, 256>>>(A_log + (size_t)l * DIN * NS,
                                              Dvec + (size_t)l * DIN);

        // out_proj + residual: (2048 x 768), K=1536
        {
            dim3 g(DD / 128, MROWS / 128);
            tgemm_kernel<<<g, 256>>>(y, out_projw + (size_t)l * DD * DIN,
                                     nullptr, x, x,
                                     MROWS, DD, DIN, DIN, DD, 0);
        }
    }

    // logits: (2048 x 32000), K=768, + bias
    {
        dim3 g(VV / 128, MROWS / 128);
        tgemm_kernel<<<g, 256>>>(x, Wout_w, Wout_b, nullptr, out,
                                 MROWS, VV, DD, DD, VV, 0);
    }
}